// round 9
// baseline (speedup 1.0000x reference)
#include <cuda_runtime.h>
#include <cuda_fp16.h>
#include <cstdint>

// ---------------------------------------------------------------------------
// LCN_4698694222614 — fused persistent kernel, v3.
//   B=512, IN=16384, DIMS={8192,4096,2048}, K=32, OUT=16
// Changes vs v2: no smem / no __syncthreads in layer loops (knn/w broadcast
// via warp shuffle), __launch_bounds__(128,10) -> 51-reg cap, 62.5% occ,
// grid = 10 blocks/SM. Explicit MLP-4 gather pipeline retained.
// ---------------------------------------------------------------------------

#define BATCH 512
#define KNN   32
#define NBAR  4          // grid barriers per launch
#define FULL  0xFFFFFFFFu

// scratch (device globals: allocation-free rule)
__device__ __half g_xT[16384 * BATCH];   // 16 MB
__device__ __half g_y0[ 8192 * BATCH];   //  8 MB
__device__ __half g_y1[ 4096 * BATCH];   //  4 MB
__device__ __half g_y2[ 2048 * BATCH];   //  2 MB
__device__ unsigned long long g_arrivals = 0;   // never reset (monotonic)

// ---- grid barrier: k-th barrier of this launch (k = 1..NBAR) --------------
__device__ __forceinline__ void grid_barrier(int k, int nb, unsigned long long base)
{
    __syncthreads();
    if (threadIdx.x == 0) {
        __threadfence();                       // release phase writes
        atomicAdd(&g_arrivals, 1ULL);
        const unsigned long long target = base + (unsigned long long)k * nb;
        while (*(volatile unsigned long long*)&g_arrivals < target)
            __nanosleep(64);
        __threadfence();                       // acquire others' writes
    }
    __syncthreads();
}

// ---- one LCN layer: 1 j per warp-pair, shuffle-broadcast idx/w, MLP=4 -----
__device__ __forceinline__ void run_layer(const __half* __restrict__ srcT,
                                          const int*    __restrict__ knn,
                                          int kstride,
                                          const float*  __restrict__ w,
                                          const float*  __restrict__ bias,
                                          __half*       __restrict__ dstT,
                                          int d, int bid, int nb)
{
    const int tid     = threadIdx.x;
    const int half_id = tid >> 6;       // which j of the block's pair
    const int t64     = tid & 63;       // 0..63: batch-slice owner
    const int lane    = tid & 31;
    const uint4* src4 = (const uint4*)srcT;

    for (int j = (bid << 1) + half_id; j < d; j += (nb << 1)) {
        // both warps of the pair load the same 128B knn/w rows (L1 broadcast)
        const int   my_idx = knn[((size_t)j * KNN + lane) * kstride];
        const float my_w   = w[(size_t)j * KNN + lane];

        // explicit 4-deep pipeline: 4 gathers in flight per thread
        uint4 pre[4];
#pragma unroll
        for (int p = 0; p < 4; ++p) {
            const int idx = __shfl_sync(FULL, my_idx, p);
            pre[p] = __ldg(&src4[(size_t)idx * 64 + t64]);
        }

        float a0 = 0.f, a1 = 0.f, a2 = 0.f, a3 = 0.f;
        float a4 = 0.f, a5 = 0.f, a6 = 0.f, a7 = 0.f;
#pragma unroll
        for (int k = 0; k < KNN; ++k) {
            const uint4 raw = pre[k & 3];
            if (k + 4 < KNN) {
                const int idx = __shfl_sync(FULL, my_idx, k + 4);
                pre[k & 3] = __ldg(&src4[(size_t)idx * 64 + t64]);
            }
            const float wk = __shfl_sync(FULL, my_w, k);
            const float2 f0 = __half22float2(*(const __half2*)&raw.x);
            const float2 f1 = __half22float2(*(const __half2*)&raw.y);
            const float2 f2 = __half22float2(*(const __half2*)&raw.z);
            const float2 f3 = __half22float2(*(const __half2*)&raw.w);
            a0 = fmaf(f0.x, wk, a0);  a1 = fmaf(f0.y, wk, a1);
            a2 = fmaf(f1.x, wk, a2);  a3 = fmaf(f1.y, wk, a3);
            a4 = fmaf(f2.x, wk, a4);  a5 = fmaf(f2.y, wk, a5);
            a6 = fmaf(f3.x, wk, a6);  a7 = fmaf(f3.y, wk, a7);
        }
        const float bb = bias[j];
        a0 = fmaxf(a0 + bb, 0.f);  a1 = fmaxf(a1 + bb, 0.f);
        a2 = fmaxf(a2 + bb, 0.f);  a3 = fmaxf(a3 + bb, 0.f);
        a4 = fmaxf(a4 + bb, 0.f);  a5 = fmaxf(a5 + bb, 0.f);
        a6 = fmaxf(a6 + bb, 0.f);  a7 = fmaxf(a7 + bb, 0.f);

        uint4 outv;
        *(__half2*)&outv.x = __floats2half2_rn(a0, a1);
        *(__half2*)&outv.y = __floats2half2_rn(a2, a3);
        *(__half2*)&outv.z = __floats2half2_rn(a4, a5);
        *(__half2*)&outv.w = __floats2half2_rn(a6, a7);
        ((uint4*)dstT)[(size_t)j * 64 + t64] = outv;
    }
}

// ---- the single fused kernel ---------------------------------------------
__global__ void __launch_bounds__(128, 10)
fused_kernel(const float* __restrict__ x,
             const int* __restrict__ k0, const float* __restrict__ w0, const float* __restrict__ b0,
             const int* __restrict__ k1, const float* __restrict__ w1, const float* __restrict__ b1,
             const int* __restrict__ k2, const float* __restrict__ w2, const float* __restrict__ b2,
             const float* __restrict__ fcw, const float* __restrict__ fcb,
             float* __restrict__ out, int nb)
{
    __shared__ float tile[32][33];

    const int tid = threadIdx.x;
    const int bid = blockIdx.x;

    // launch-base of the monotonic barrier counter
    const unsigned long long ARR  = (unsigned long long)NBAR * nb;
    const unsigned long long snap = *(volatile unsigned long long*)&g_arrivals;
    const unsigned long long base = snap - (snap % ARR);

    // knn dtype probe (per warp): int64 LE => odd 32-bit words all zero
    int kstride;
    {
        const int lane = tid & 31;
        int v = k0[2 * lane + 1];
        unsigned any = __ballot_sync(FULL, v != 0);
        kstride = any ? 1 : 2;
    }

    // ---- phase 0: transpose x (512,16384) fp32 -> xT (16384,512) fp16 ----
    {
        const int tx = tid & 31, ty0 = tid >> 5;       // 32 x 4
        for (int t = bid; t < 8192; t += nb) {          // 512 c-tiles x 16 b-tiles
            const int c0  = (t & 511) << 5;
            const int b0t = (t >> 9) << 5;
            __syncthreads();
#pragma unroll
            for (int i = 0; i < 32; i += 4)
                tile[ty0 + i][tx] = x[(size_t)(b0t + ty0 + i) * 16384 + (c0 + tx)];
            __syncthreads();
#pragma unroll
            for (int i = 0; i < 32; i += 4)
                g_xT[(size_t)(c0 + ty0 + i) * BATCH + (b0t + tx)] =
                    __float2half_rn(tile[tx][ty0 + i]);
        }
        if (bid == 0)                                   // bias-init output
            for (int i = tid; i < BATCH * 16; i += 128)
                out[i] = fcb[i & 15];
    }

    grid_barrier(1, nb, base);
    run_layer(g_xT, k0, kstride, w0, b0, g_y0, 8192, bid, nb);
    grid_barrier(2, nb, base);
    run_layer(g_y0, k1, kstride, w1, b1, g_y1, 4096, bid, nb);
    grid_barrier(3, nb, base);
    run_layer(g_y1, k2, kstride, w2, b2, g_y2, 2048, bid, nb);
    grid_barrier(4, nb, base);

    // ---- phase 4: FC  out[b,o] += sum_j y2T[j,b] * fcw[j,o] --------------
    // 256 blocks: 4 batch tiles x 64 j-tiles of 32
    if (bid < 256) {
        const int b  = (bid & 3) * 128 + tid;
        const int j0 = (bid >> 2) * 32;
        float acc[16];
#pragma unroll
        for (int o = 0; o < 16; ++o) acc[o] = 0.f;
#pragma unroll 4
        for (int jj = 0; jj < 32; ++jj) {
            const int   j = j0 + jj;
            const float v = __half2float(g_y2[(size_t)j * BATCH + b]);
#pragma unroll
            for (int o = 0; o < 16; ++o)
                acc[o] = fmaf(v, __ldg(&fcw[j * 16 + o]), acc[o]);
        }
#pragma unroll
        for (int o = 0; o < 16; ++o)
            atomicAdd(&out[b * 16 + o], acc[o]);
    }
}

// ---------------------------------------------------------------------------
extern "C" void kernel_launch(void* const* d_in, const int* in_sizes, int n_in,
                              void* d_out, int out_size)
{
    const float *x, *w0, *b0, *w1, *b1, *w2, *b2, *fcw, *fcb;
    const int *k0, *k1, *k2;

    // Disambiguate metadata ordering via element counts:
    //   dict order:      x,w0,b0,knn0,w1,b1,knn1,w2,b2,knn2,fc_w,fc_b
    //   signature order: x,w0,b0,w1,b1,w2,b2,fc_w,fc_b,knn0,knn1,knn2
    if (in_sizes[3] == 262144) {
        x   = (const float*)d_in[0];
        w0  = (const float*)d_in[1];  b0 = (const float*)d_in[2];
        k0  = (const int*)d_in[3];
        w1  = (const float*)d_in[4];  b1 = (const float*)d_in[5];
        k1  = (const int*)d_in[6];
        w2  = (const float*)d_in[7];  b2 = (const float*)d_in[8];
        k2  = (const int*)d_in[9];
        fcw = (const float*)d_in[10]; fcb = (const float*)d_in[11];
    } else {
        x   = (const float*)d_in[0];
        w0  = (const float*)d_in[1];  b0 = (const float*)d_in[2];
        w1  = (const float*)d_in[3];  b1 = (const float*)d_in[4];
        w2  = (const float*)d_in[5];  b2 = (const float*)d_in[6];
        fcw = (const float*)d_in[7];  fcb = (const float*)d_in[8];
        k0  = (const int*)d_in[9];
        k1  = (const int*)d_in[10];
        k2  = (const int*)d_in[11];
    }

    int dev = 0, sms = 148;
    cudaGetDevice(&dev);
    cudaDeviceGetAttribute(&sms, cudaDevAttrMultiProcessorCount, dev);
    const int nb = sms * 10;       // co-resident by __launch_bounds__(128, 10)

    fused_kernel<<<nb, 128>>>(x, k0, w0, b0, k1, w1, b1, k2, w2, b2,
                              fcw, fcb, (float*)d_out, nb);
}

// round 10
// speedup vs baseline: 1.1514x; 1.1514x over previous
#include <cuda_runtime.h>
#include <cuda_fp16.h>
#include <cstdint>

// ---------------------------------------------------------------------------
// LCN_4698694222614 — fused persistent kernel, v4 (= v2/R8 + knn/w prefetch).
//   B=512, IN=16384, DIMS={8192,4096,2048}, K=32, OUT=16
// Phases: transpose(x)->fp16 xT | L0 | L1 | L2 | FC, separated by a
// graph-replay-safe grid barrier (monotonic arrival counter).
// Layer loop: 2 j per 128-thr block, smem-staged idx/w (double-buffered,
// register-prefetched), explicit MLP-4 gather pipeline, 16B loads.
// ---------------------------------------------------------------------------

#define BATCH 512
#define KNN   32
#define NBAR  4          // grid barriers per launch
#define FULL  0xFFFFFFFFu

// scratch (device globals: allocation-free rule)
__device__ __half g_xT[16384 * BATCH];   // 16 MB
__device__ __half g_y0[ 8192 * BATCH];   //  8 MB
__device__ __half g_y1[ 4096 * BATCH];   //  4 MB
__device__ __half g_y2[ 2048 * BATCH];   //  2 MB
__device__ unsigned long long g_arrivals = 0;   // never reset (monotonic)

// ---- grid barrier: k-th barrier of this launch (k = 1..NBAR) --------------
__device__ __forceinline__ void grid_barrier(int k, int nb, unsigned long long base)
{
    __syncthreads();
    if (threadIdx.x == 0) {
        __threadfence();                       // release phase writes
        atomicAdd(&g_arrivals, 1ULL);
        const unsigned long long target = base + (unsigned long long)k * nb;
        while (*(volatile unsigned long long*)&g_arrivals < target)
            __nanosleep(64);
        __threadfence();                       // acquire others' writes
    }
    __syncthreads();
}

// ---- one LCN layer phase: 2 j per 128-thr block, 16B gathers, MLP=4 -------
__device__ __forceinline__ void run_layer(const __half* __restrict__ srcT,
                                          const int*    __restrict__ knn,
                                          int kstride,
                                          const float*  __restrict__ w,
                                          const float*  __restrict__ bias,
                                          __half*       __restrict__ dstT,
                                          int d, int bid, int nb,
                                          int (*s_idx)[64], float (*s_w)[64])
{
    const int tid     = threadIdx.x;
    const int half_id = tid >> 6;       // which j of the pair
    const int t64     = tid & 63;
    const uint4* src4 = (const uint4*)srcT;
    const int npairs  = d >> 1;

    // register prefetch of the first pair's idx/w (hides staging latency)
    int nidx = 0; float nw = 0.f;
    if (tid < 64 && bid < npairs) {
        const int jj = (bid << 1) + (tid >> 5);
        const int kk = tid & 31;
        nidx = knn[((size_t)jj * KNN + kk) * kstride];
        nw   = w[(size_t)jj * KNN + kk];
    }

    int it = 0;
    for (int pair = bid; pair < npairs; pair += nb, ++it) {
        const int buf = it & 1;
        if (tid < 64) {                        // stage prefetched pair
            s_idx[buf][tid] = nidx;
            s_w[buf][tid]   = nw;
        }
        __syncthreads();                       // one sync per iteration

        // immediately prefetch the NEXT pair (overlaps with gather below)
        const int np = pair + nb;
        if (tid < 64 && np < npairs) {
            const int jj = (np << 1) + (tid >> 5);
            const int kk = tid & 31;
            nidx = knn[((size_t)jj * KNN + kk) * kstride];
            nw   = w[(size_t)jj * KNN + kk];
        }

        const int    j    = (pair << 1) + half_id;
        const int*   sidx = s_idx[buf] + (half_id << 5);
        const float* sw   = s_w[buf]   + (half_id << 5);

        // explicit 4-deep pipeline: guaranteed 4 gathers in flight
        uint4 pre[4];
#pragma unroll
        for (int p = 0; p < 4; ++p)
            pre[p] = __ldg(&src4[(size_t)sidx[p] * 64 + t64]);

        float a0 = 0.f, a1 = 0.f, a2 = 0.f, a3 = 0.f;
        float a4 = 0.f, a5 = 0.f, a6 = 0.f, a7 = 0.f;
#pragma unroll
        for (int k = 0; k < KNN; ++k) {
            const uint4 raw = pre[k & 3];
            if (k + 4 < KNN)
                pre[k & 3] = __ldg(&src4[(size_t)sidx[k + 4] * 64 + t64]);
            const float2 f0 = __half22float2(*(const __half2*)&raw.x);
            const float2 f1 = __half22float2(*(const __half2*)&raw.y);
            const float2 f2 = __half22float2(*(const __half2*)&raw.z);
            const float2 f3 = __half22float2(*(const __half2*)&raw.w);
            const float  wk = sw[k];
            a0 = fmaf(f0.x, wk, a0);  a1 = fmaf(f0.y, wk, a1);
            a2 = fmaf(f1.x, wk, a2);  a3 = fmaf(f1.y, wk, a3);
            a4 = fmaf(f2.x, wk, a4);  a5 = fmaf(f2.y, wk, a5);
            a6 = fmaf(f3.x, wk, a6);  a7 = fmaf(f3.y, wk, a7);
        }
        const float bb = bias[j];
        a0 = fmaxf(a0 + bb, 0.f);  a1 = fmaxf(a1 + bb, 0.f);
        a2 = fmaxf(a2 + bb, 0.f);  a3 = fmaxf(a3 + bb, 0.f);
        a4 = fmaxf(a4 + bb, 0.f);  a5 = fmaxf(a5 + bb, 0.f);
        a6 = fmaxf(a6 + bb, 0.f);  a7 = fmaxf(a7 + bb, 0.f);

        uint4 outv;
        *(__half2*)&outv.x = __floats2half2_rn(a0, a1);
        *(__half2*)&outv.y = __floats2half2_rn(a2, a3);
        *(__half2*)&outv.z = __floats2half2_rn(a4, a5);
        *(__half2*)&outv.w = __floats2half2_rn(a6, a7);
        ((uint4*)dstT)[(size_t)j * 64 + t64] = outv;
    }
}

// ---- the single fused kernel ---------------------------------------------
__global__ void __launch_bounds__(128, 8)
fused_kernel(const float* __restrict__ x,
             const int* __restrict__ k0, const float* __restrict__ w0, const float* __restrict__ b0,
             const int* __restrict__ k1, const float* __restrict__ w1, const float* __restrict__ b1,
             const int* __restrict__ k2, const float* __restrict__ w2, const float* __restrict__ b2,
             const float* __restrict__ fcw, const float* __restrict__ fcb,
             float* __restrict__ out, int nb)
{
    __shared__ float tile[32][33];
    __shared__ int   s_idx[2][64];
    __shared__ float s_w[2][64];

    const int tid = threadIdx.x;
    const int bid = blockIdx.x;

    // launch-base of the monotonic barrier counter
    const unsigned long long ARR  = (unsigned long long)NBAR * nb;
    const unsigned long long snap = *(volatile unsigned long long*)&g_arrivals;
    const unsigned long long base = snap - (snap % ARR);

    // knn dtype probe (per warp): int64 LE => odd 32-bit words all zero
    int kstride;
    {
        const int lane = tid & 31;
        int v = k0[2 * lane + 1];
        unsigned any = __ballot_sync(FULL, v != 0);
        kstride = any ? 1 : 2;
    }

    // ---- phase 0: transpose x (512,16384) fp32 -> xT (16384,512) fp16 ----
    {
        const int tx = tid & 31, ty0 = tid >> 5;       // 32 x 4
        for (int t = bid; t < 8192; t += nb) {          // 512 c-tiles x 16 b-tiles
            const int c0  = (t & 511) << 5;
            const int b0t = (t >> 9) << 5;
            __syncthreads();
#pragma unroll
            for (int i = 0; i < 32; i += 4)
                tile[ty0 + i][tx] = x[(size_t)(b0t + ty0 + i) * 16384 + (c0 + tx)];
            __syncthreads();
#pragma unroll
            for (int i = 0; i < 32; i += 4)
                g_xT[(size_t)(c0 + ty0 + i) * BATCH + (b0t + tx)] =
                    __float2half_rn(tile[tx][ty0 + i]);
        }
        if (bid == 0)                                   // bias-init output
            for (int i = tid; i < BATCH * 16; i += 128)
                out[i] = fcb[i & 15];
    }

    grid_barrier(1, nb, base);
    run_layer(g_xT, k0, kstride, w0, b0, g_y0, 8192, bid, nb, s_idx, s_w);
    grid_barrier(2, nb, base);
    run_layer(g_y0, k1, kstride, w1, b1, g_y1, 4096, bid, nb, s_idx, s_w);
    grid_barrier(3, nb, base);
    run_layer(g_y1, k2, kstride, w2, b2, g_y2, 2048, bid, nb, s_idx, s_w);
    grid_barrier(4, nb, base);

    // ---- phase 4: FC  out[b,o] += sum_j y2T[j,b] * fcw[j,o] --------------
    // 256 blocks: 4 batch tiles x 64 j-tiles of 32
    if (bid < 256) {
        const int b  = (bid & 3) * 128 + tid;
        const int j0 = (bid >> 2) * 32;
        float acc[16];
#pragma unroll
        for (int o = 0; o < 16; ++o) acc[o] = 0.f;
#pragma unroll 4
        for (int jj = 0; jj < 32; ++jj) {
            const int   j = j0 + jj;
            const float v = __half2float(g_y2[(size_t)j * BATCH + b]);
#pragma unroll
            for (int o = 0; o < 16; ++o)
                acc[o] = fmaf(v, __ldg(&fcw[j * 16 + o]), acc[o]);
        }
#pragma unroll
        for (int o = 0; o < 16; ++o)
            atomicAdd(&out[b * 16 + o], acc[o]);
    }
}

// ---------------------------------------------------------------------------
extern "C" void kernel_launch(void* const* d_in, const int* in_sizes, int n_in,
                              void* d_out, int out_size)
{
    const float *x, *w0, *b0, *w1, *b1, *w2, *b2, *fcw, *fcb;
    const int *k0, *k1, *k2;

    // Disambiguate metadata ordering via element counts:
    //   dict order:      x,w0,b0,knn0,w1,b1,knn1,w2,b2,knn2,fc_w,fc_b
    //   signature order: x,w0,b0,w1,b1,w2,b2,fc_w,fc_b,knn0,knn1,knn2
    if (in_sizes[3] == 262144) {
        x   = (const float*)d_in[0];
        w0  = (const float*)d_in[1];  b0 = (const float*)d_in[2];
        k0  = (const int*)d_in[3];
        w1  = (const float*)d_in[4];  b1 = (const float*)d_in[5];
        k1  = (const int*)d_in[6];
        w2  = (const float*)d_in[7];  b2 = (const float*)d_in[8];
        k2  = (const int*)d_in[9];
        fcw = (const float*)d_in[10]; fcb = (const float*)d_in[11];
    } else {
        x   = (const float*)d_in[0];
        w0  = (const float*)d_in[1];  b0 = (const float*)d_in[2];
        w1  = (const float*)d_in[3];  b1 = (const float*)d_in[4];
        w2  = (const float*)d_in[5];  b2 = (const float*)d_in[6];
        fcw = (const float*)d_in[7];  fcb = (const float*)d_in[8];
        k0  = (const int*)d_in[9];
        k1  = (const int*)d_in[10];
        k2  = (const int*)d_in[11];
    }

    int dev = 0, sms = 148;
    cudaGetDevice(&dev);
    cudaDeviceGetAttribute(&sms, cudaDevAttrMultiProcessorCount, dev);
    const int nb = sms * 8;        // co-resident by __launch_bounds__(128, 8)

    fused_kernel<<<nb, 128>>>(x, k0, w0, b0, k1, w1, b1, k2, w2, b2,
                              fcw, fcb, (float*)d_out, nb);
}